// round 7
// baseline (speedup 1.0000x reference)
#include <cuda_runtime.h>
#include <cstdint>

#define NMAX 50000
#define EMAX 800000
#define ETMAX (EMAX + NMAX)
#define NB 512               // persistent grid: guaranteed resident (148 SM x 4 = 592 slots)
#define NTH 256
#define FEAT_BLKS 160        // phase A split: blocks [0,160) feat1, [160,512) hist
#define NCHUNK ((NMAX + 255) / 256)   // 196 scan chunks

// ---------------- scratch (device globals: allocation-free) ----------------
__device__ float g_h1[NMAX * 128];
__device__ float g_as1[NMAX * 4];
__device__ float g_ad1[NMAX * 4];
__device__ float g_h2[NMAX * 2];
__device__ float g_as2[NMAX];
__device__ float g_ad2[NMAX];
__device__ int   g_cnt[NMAX];        // zero at entry; re-zeroed in phase C each run
__device__ int   g_row[NMAX + 1];
__device__ int   g_pos[EMAX];
__device__ int   g_srcs[ETMAX];
__device__ int   g_blk[NCHUNK];
__device__ unsigned g_bar_count;
__device__ volatile unsigned g_bar_gen;

__device__ __forceinline__ float lrelu(float v) { return v > 0.f ? v : 0.2f * v; }

// grid-wide barrier (all NB blocks resident by construction)
__device__ __forceinline__ void gbar() {
    __syncthreads();
    if (threadIdx.x == 0) {
        __threadfence();
        unsigned gen = g_bar_gen;
        if (atomicAdd(&g_bar_count, 1u) == (unsigned)NB - 1u) {
            g_bar_count = 0u;
            __threadfence();
            g_bar_gen = gen + 1u;
        } else {
            while (g_bar_gen == gen) __nanosleep(64);
        }
        __threadfence();
    }
    __syncthreads();
}

__global__ void __launch_bounds__(NTH, 4) mega(
    const float* __restrict__ x, const int* __restrict__ ei,
    const float* __restrict__ W1, const float* __restrict__ as1w,
    const float* __restrict__ ad1w, const float* __restrict__ b1,
    const float* __restrict__ W2, const float* __restrict__ as2w,
    const float* __restrict__ ad2w, const float* __restrict__ b2,
    float* __restrict__ out, int n, int Eo)
{
    __shared__ float Ws[16 * 128];                // feat1 weights / int scratch
    int* sInt = (int*)Ws;
    const int b = blockIdx.x, tid = threadIdx.x;
    const int lane = tid & 31, wp = tid >> 5;

    // ===== Phase A: feat1 (blocks < FEAT_BLKS) || hist (rest) ==============
    if (b < FEAT_BLKS) {
        for (int i = tid; i < 16 * 128; i += NTH) Ws[i] = W1[i];
        __syncthreads();
        int slot = tid >> 7;          // 0..1 (two nodes per block iteration)
        int c = tid & 127;            // channel
        int head = c >> 5;
        float as = as1w[c], ad = ad1w[c];
        for (int nn = b * 2 + slot; nn < n; nn += FEAT_BLKS * 2) {
            const float4* xr = (const float4*)(x + (size_t)nn * 16);
            float4 x0 = xr[0], x1 = xr[1], x2 = xr[2], x3 = xr[3];
            float acc;
            acc  = x0.x * Ws[c];        acc += x0.y * Ws[128 + c];
            acc += x0.z * Ws[256 + c];  acc += x0.w * Ws[384 + c];
            acc += x1.x * Ws[512 + c];  acc += x1.y * Ws[640 + c];
            acc += x1.z * Ws[768 + c];  acc += x1.w * Ws[896 + c];
            acc += x2.x * Ws[1024 + c]; acc += x2.y * Ws[1152 + c];
            acc += x2.z * Ws[1280 + c]; acc += x2.w * Ws[1408 + c];
            acc += x3.x * Ws[1536 + c]; acc += x3.y * Ws[1664 + c];
            acc += x3.z * Ws[1792 + c]; acc += x3.w * Ws[1920 + c];
            g_h1[(size_t)nn * 128 + c] = acc;
            float s = acc * as, d = acc * ad;
            #pragma unroll
            for (int o = 16; o; o >>= 1) {
                s += __shfl_down_sync(0xffffffffu, s, o);
                d += __shfl_down_sync(0xffffffffu, d, o);
            }
            if (lane == 0) { g_as1[nn * 4 + head] = s; g_ad1[nn * 4 + head] = d; }
        }
    } else {
        const int hb = b - FEAT_BLKS;
        const int stride = (NB - FEAT_BLKS) * NTH;
        for (int e = hb * NTH + tid; e < Eo; e += stride)
            g_pos[e] = atomicAdd(g_cnt + ei[Eo + e], 1);
    }
    gbar();

    // ===== Phase B: per-chunk sums of (cnt+1) ==============================
    if (b < NCHUNK) {
        int i = b * 256 + tid;
        int v = (i < n) ? (g_cnt[i] + 1) : 0;
        // warp reduce then cross-warp
        int s = v;
        #pragma unroll
        for (int o = 16; o; o >>= 1) s += __shfl_down_sync(0xffffffffu, s, o);
        __syncthreads();
        if (lane == 0) sInt[wp] = s;
        __syncthreads();
        if (tid == 0) {
            int tot = 0;
            #pragma unroll
            for (int k = 0; k < 8; k++) tot += sInt[k];
            g_blk[b] = tot;
        }
    }
    gbar();

    // ===== Phase C: row starts (self spine prefix + local scan), reset cnt ==
    if (b < NCHUNK) {
        // spine prefix: sum g_blk[0..b)
        int part = 0;
        for (int j = tid; j < b; j += NTH) part += g_blk[j];
        int ps = part;
        #pragma unroll
        for (int o = 16; o; o >>= 1) ps += __shfl_down_sync(0xffffffffu, ps, o);
        __syncthreads();
        if (lane == 0) sInt[wp] = ps;
        __syncthreads();
        int spine = sInt[0] + sInt[1] + sInt[2] + sInt[3]
                  + sInt[4] + sInt[5] + sInt[6] + sInt[7];
        __syncthreads();
        // local scan of (cnt+1)
        int i = b * 256 + tid;
        int v = (i < n) ? (g_cnt[i] + 1) : 0;
        int s = v;
        #pragma unroll
        for (int o = 1; o < 32; o <<= 1) {
            int u = __shfl_up_sync(0xffffffffu, s, o);
            if (lane >= o) s += u;
        }
        if (lane == 31) sInt[8 + wp] = s;
        __syncthreads();
        if (wp == 0 && lane < 8) {
            int ws = sInt[8 + lane];
            #pragma unroll
            for (int o = 1; o < 8; o <<= 1) {
                int u = __shfl_up_sync(0x000000ffu, ws, o);
                if (lane >= o) ws += u;
            }
            sInt[8 + lane] = ws;
        }
        __syncthreads();
        int base = spine + (wp ? sInt[8 + wp - 1] : 0);
        if (i < n) {
            int pre = base + s - v;
            g_row[i] = pre;
            g_cnt[i] = 0;                    // re-arm for next replay
            if (i == n - 1) g_row[n] = pre + v;
        }
    }
    gbar();

    // ===== Phase D: atomic-free scatter ====================================
    {
        const int stride = NB * NTH;
        for (int e = b * NTH + tid; e < Eo; e += stride) {
            int s = ei[e], d = ei[Eo + e];
            g_srcs[g_row[d] + 1 + g_pos[e]] = s;
        }
        for (int i = b * NTH + tid; i < n; i += stride)
            g_srcs[g_row[i]] = i;            // self loop at slot 0
    }
    gbar();

    // ===== Phase E: layer1 gather + normalize + relu + W2 proj =============
    {
        const int gw0 = (b * NTH + tid) >> 5;
        const int head = lane >> 3;
        const int c0 = lane * 4;
        float4 bb = *(const float4*)(b1 + c0);
        float4 wA = *(const float4*)(W2 + c0 * 2);
        float4 wB = *(const float4*)(W2 + c0 * 2 + 4);
        float sa0 = as2w[0], sa1 = as2w[1], da0 = ad2w[0], da1 = ad2w[1];
        for (int d = gw0; d < n; d += NB * 8) {
            float adh = g_ad1[d * 4 + head];
            float ax = 0.f, ay = 0.f, az = 0.f, aw = 0.f, den = 0.f;
            int p = g_row[d], pend = g_row[d + 1];
            for (; p + 4 <= pend; p += 4) {
                int s0 = __ldg(g_srcs + p);
                int s1 = __ldg(g_srcs + p + 1);
                int s2 = __ldg(g_srcs + p + 2);
                int s3 = __ldg(g_srcs + p + 3);
                float l0 = __ldg(g_as1 + s0 * 4 + head);
                float l1 = __ldg(g_as1 + s1 * 4 + head);
                float l2 = __ldg(g_as1 + s2 * 4 + head);
                float l3 = __ldg(g_as1 + s3 * 4 + head);
                float4 h0 = *(const float4*)(g_h1 + (size_t)s0 * 128 + c0);
                float4 h1 = *(const float4*)(g_h1 + (size_t)s1 * 128 + c0);
                float4 h2 = *(const float4*)(g_h1 + (size_t)s2 * 128 + c0);
                float4 h3 = *(const float4*)(g_h1 + (size_t)s3 * 128 + c0);
                float w0 = __expf(lrelu(l0 + adh));
                float w1 = __expf(lrelu(l1 + adh));
                float w2 = __expf(lrelu(l2 + adh));
                float w3 = __expf(lrelu(l3 + adh));
                den += (w0 + w1) + (w2 + w3);
                ax = fmaf(w0, h0.x, ax); ay = fmaf(w0, h0.y, ay);
                az = fmaf(w0, h0.z, az); aw = fmaf(w0, h0.w, aw);
                ax = fmaf(w1, h1.x, ax); ay = fmaf(w1, h1.y, ay);
                az = fmaf(w1, h1.z, az); aw = fmaf(w1, h1.w, aw);
                ax = fmaf(w2, h2.x, ax); ay = fmaf(w2, h2.y, ay);
                az = fmaf(w2, h2.z, az); aw = fmaf(w2, h2.w, aw);
                ax = fmaf(w3, h3.x, ax); ay = fmaf(w3, h3.y, ay);
                az = fmaf(w3, h3.z, az); aw = fmaf(w3, h3.w, aw);
            }
            for (; p < pend; ++p) {
                int s = __ldg(g_srcs + p);
                float w = __expf(lrelu(__ldg(g_as1 + s * 4 + head) + adh));
                den += w;
                float4 h = *(const float4*)(g_h1 + (size_t)s * 128 + c0);
                ax = fmaf(w, h.x, ax); ay = fmaf(w, h.y, ay);
                az = fmaf(w, h.z, az); aw = fmaf(w, h.w, aw);
            }
            float inv = 1.f / (den + 1e-16f);
            float v0 = fmaxf(ax * inv + bb.x, 0.f);
            float v1 = fmaxf(ay * inv + bb.y, 0.f);
            float v2 = fmaxf(az * inv + bb.z, 0.f);
            float v3 = fmaxf(aw * inv + bb.w, 0.f);
            float pq0 = v0 * wA.x + v1 * wA.z + v2 * wB.x + v3 * wB.z;
            float pq1 = v0 * wA.y + v1 * wA.w + v2 * wB.y + v3 * wB.w;
            #pragma unroll
            for (int o = 16; o; o >>= 1) {
                pq0 += __shfl_down_sync(0xffffffffu, pq0, o);
                pq1 += __shfl_down_sync(0xffffffffu, pq1, o);
            }
            if (lane == 0) {
                g_h2[d * 2] = pq0; g_h2[d * 2 + 1] = pq1;
                g_as2[d] = pq0 * sa0 + pq1 * sa1;
                g_ad2[d] = pq0 * da0 + pq1 * da1;
            }
        }
    }
    gbar();

    // ===== Phase F: layer2 gather -> output ================================
    {
        const int gw0 = (b * NTH + tid) >> 5;
        float bb0 = b2[0], bb1 = b2[1];
        for (int d = gw0; d < n; d += NB * 8) {
            float add = g_ad2[d];
            float wsum = 0.f, s0 = 0.f, s1 = 0.f;
            int p0 = g_row[d], pend = g_row[d + 1];
            for (int p = p0 + lane; p < pend; p += 32) {
                int s = __ldg(g_srcs + p);
                float w = __expf(lrelu(__ldg(g_as2 + s) + add));
                wsum += w;
                float2 h = *(const float2*)(g_h2 + s * 2);
                s0 = fmaf(w, h.x, s0);
                s1 = fmaf(w, h.y, s1);
            }
            #pragma unroll
            for (int o = 16; o; o >>= 1) {
                wsum += __shfl_down_sync(0xffffffffu, wsum, o);
                s0   += __shfl_down_sync(0xffffffffu, s0, o);
                s1   += __shfl_down_sync(0xffffffffu, s1, o);
            }
            if (lane == 0) {
                float inv = 1.f / (wsum + 1e-16f);
                out[d * 2]     = s0 * inv + bb0;
                out[d * 2 + 1] = s1 * inv + bb1;
            }
        }
    }
}

extern "C" void kernel_launch(void* const* d_in, const int* in_sizes, int n_in,
                              void* d_out, int out_size) {
    const float* x   = (const float*)d_in[0];
    const int*   ei  = (const int*)d_in[1];
    const float* W1  = (const float*)d_in[2];
    const float* as1 = (const float*)d_in[3];
    const float* ad1 = (const float*)d_in[4];
    const float* b1  = (const float*)d_in[5];
    const float* W2  = (const float*)d_in[6];
    const float* as2 = (const float*)d_in[7];
    const float* ad2 = (const float*)d_in[8];
    const float* b2  = (const float*)d_in[9];
    float* out = (float*)d_out;

    int n  = in_sizes[0] / 16;   // nodes
    int Eo = in_sizes[1] / 2;    // original edges

    mega<<<NB, NTH>>>(x, ei, W1, as1, ad1, b1, W2, as2, ad2, b2, out, n, Eo);
}

// round 8
// speedup vs baseline: 1.3684x; 1.3684x over previous
#include <cuda_runtime.h>
#include <cstdint>

#define NMAX 50000
#define EMAX 800000
#define ETMAX (EMAX + NMAX)
#define NCHUNK ((NMAX + 255) / 256)   // 196
#define READY  (1 << 30)
#define VMASK  (READY - 1)

// ---------------- scratch (device globals: allocation-free) ----------------
__device__ float g_h1[NMAX * 128];
__device__ float g_as1[NMAX * 4];
__device__ float g_ad1[NMAX * 4];
__device__ float g_h2[NMAX * 2];
__device__ float g_as2[NMAX];
__device__ float g_ad2[NMAX];
__device__ int   g_cnt[NMAX];      // zero at entry; re-zeroed by k_scan each run
__device__ int   g_row[NMAX + 1];
__device__ int   g_pos[EMAX];
__device__ int   g_srcs[ETMAX];
__device__ int   g_blk[NCHUNK];    // packed (sum | READY); reset by k_scatter

__device__ __forceinline__ float lrelu(float v) { return v > 0.f ? v : 0.2f * v; }

// ---------------- kernel 1: feat1 (blocks < FB) || hist (rest) -------------
#define FB 400
#define HB 400
__global__ void k_feathist(const float* __restrict__ x, const int* __restrict__ ei,
                           const float* __restrict__ W1, const float* __restrict__ a_src1,
                           const float* __restrict__ a_dst1, int n, int Eo) {
    __shared__ float Ws[16 * 128];
    const int b = blockIdx.x, tid = threadIdx.x, lane = tid & 31;
    if (b < FB) {
        for (int i = tid; i < 16 * 128; i += 256) Ws[i] = W1[i];
        __syncthreads();
        int slot = tid >> 7;           // 2 nodes per block iteration
        int c = tid & 127;
        int head = c >> 5;
        float as = a_src1[c], ad = a_dst1[c];
        for (int nn = b * 2 + slot; nn < n; nn += FB * 2) {
            const float4* xr = (const float4*)(x + (size_t)nn * 16);
            float4 x0 = xr[0], x1 = xr[1], x2 = xr[2], x3 = xr[3];
            float acc;
            acc  = x0.x * Ws[c];        acc += x0.y * Ws[128 + c];
            acc += x0.z * Ws[256 + c];  acc += x0.w * Ws[384 + c];
            acc += x1.x * Ws[512 + c];  acc += x1.y * Ws[640 + c];
            acc += x1.z * Ws[768 + c];  acc += x1.w * Ws[896 + c];
            acc += x2.x * Ws[1024 + c]; acc += x2.y * Ws[1152 + c];
            acc += x2.z * Ws[1280 + c]; acc += x2.w * Ws[1408 + c];
            acc += x3.x * Ws[1536 + c]; acc += x3.y * Ws[1664 + c];
            acc += x3.z * Ws[1792 + c]; acc += x3.w * Ws[1920 + c];
            g_h1[(size_t)nn * 128 + c] = acc;
            float s = acc * as, d = acc * ad;
            #pragma unroll
            for (int o = 16; o; o >>= 1) {
                s += __shfl_down_sync(0xffffffffu, s, o);
                d += __shfl_down_sync(0xffffffffu, d, o);
            }
            if (lane == 0) { g_as1[nn * 4 + head] = s; g_ad1[nn * 4 + head] = d; }
        }
    } else {
        const int hb = b - FB;
        const int stride = HB * 256;
        for (int e = hb * 256 + tid; e < Eo; e += stride)
            g_pos[e] = atomicAdd(g_cnt + ei[Eo + e], 1);
    }
}

// ---------------- kernel 2: fused decoupled-lookback scan -------------------
// row starts from (cnt+1); resets cnt for the next replay.
__global__ void k_scan(int n) {
    __shared__ int sh[16];   // [0..7] lookback warp sums, [8..15] scan warp sums
    const int b = blockIdx.x, tid = threadIdx.x, lane = tid & 31, wp = tid >> 5;
    int i = b * 256 + tid;
    int v = (i < n) ? (g_cnt[i] + 1) : 0;
    int s = v;
    #pragma unroll
    for (int o = 1; o < 32; o <<= 1) {
        int u = __shfl_up_sync(0xffffffffu, s, o);
        if (lane >= o) s += u;
    }
    if (lane == 31) sh[8 + wp] = s;
    __syncthreads();
    if (wp == 0 && lane < 8) {
        int ws = sh[8 + lane];
        #pragma unroll
        for (int o = 1; o < 8; o <<= 1) {
            int u = __shfl_up_sync(0x000000ffu, ws, o);
            if (lane >= o) ws += u;
        }
        sh[8 + lane] = ws;
    }
    __syncthreads();
    // publish this chunk's total (single packed word: no fence needed)
    if (tid == 0) atomicExch(g_blk + b, sh[15] | READY);
    // lookback: sum all predecessor chunk totals
    int part = 0;
    for (int j = tid; j < b; j += 256) {
        volatile int* p = (volatile int*)(g_blk + j);
        int w;
        while (((w = *p) & READY) == 0) { }
        part += w & VMASK;
    }
    #pragma unroll
    for (int o = 16; o; o >>= 1) part += __shfl_down_sync(0xffffffffu, part, o);
    if (lane == 0) sh[wp] = part;
    __syncthreads();
    int spine = sh[0] + sh[1] + sh[2] + sh[3] + sh[4] + sh[5] + sh[6] + sh[7];
    int base = spine + (wp ? sh[8 + wp - 1] : 0);
    if (i < n) {
        int pre = base + s - v;
        g_row[i] = pre;
        g_cnt[i] = 0;                 // re-arm for next replay
        if (i == n - 1) g_row[n] = pre + v;
    }
}

// ---------------- kernel 3: atomic-free scatter + flag reset ----------------
__global__ void k_scatter(const int* __restrict__ ei, int Eo, int n) {
    int gt = blockIdx.x * blockDim.x + threadIdx.x;
    if (gt < NCHUNK) g_blk[gt] = 0;   // re-arm scan flags for next replay
    int base = gt * 4;
    #pragma unroll
    for (int k = 0; k < 4; k++) {
        int e = base + k;
        if (e < Eo) {
            int s = ei[e], d = ei[Eo + e];
            g_srcs[g_row[d] + 1 + g_pos[e]] = s;
        } else {
            int i = e - Eo;
            if (i < n) g_srcs[g_row[i]] = i;   // self loop at slot 0
        }
    }
}

// ---------------- kernel 4: layer1 gather + normalize + relu + W2 proj ------
__global__ void k_gather1(const float* __restrict__ b1, const float* __restrict__ W2,
                          const float* __restrict__ a_src2, const float* __restrict__ a_dst2,
                          int n_nodes) {
    int t = blockIdx.x * blockDim.x + threadIdx.x;
    int d = t >> 5, lane = t & 31;
    if (d >= n_nodes) return;
    int head = lane >> 3;
    int c0 = lane * 4;

    float adh = g_ad1[d * 4 + head];
    float ax = 0.f, ay = 0.f, az = 0.f, aw = 0.f, den = 0.f;

    int p = g_row[d], pend = g_row[d + 1];
    for (; p + 4 <= pend; p += 4) {
        int s0 = __ldg(g_srcs + p);
        int s1 = __ldg(g_srcs + p + 1);
        int s2 = __ldg(g_srcs + p + 2);
        int s3 = __ldg(g_srcs + p + 3);
        float l0 = __ldg(g_as1 + s0 * 4 + head);
        float l1 = __ldg(g_as1 + s1 * 4 + head);
        float l2 = __ldg(g_as1 + s2 * 4 + head);
        float l3 = __ldg(g_as1 + s3 * 4 + head);
        float4 h0 = *(const float4*)(g_h1 + (size_t)s0 * 128 + c0);
        float4 h1 = *(const float4*)(g_h1 + (size_t)s1 * 128 + c0);
        float4 h2 = *(const float4*)(g_h1 + (size_t)s2 * 128 + c0);
        float4 h3 = *(const float4*)(g_h1 + (size_t)s3 * 128 + c0);
        float w0 = __expf(lrelu(l0 + adh));
        float w1 = __expf(lrelu(l1 + adh));
        float w2 = __expf(lrelu(l2 + adh));
        float w3 = __expf(lrelu(l3 + adh));
        den += (w0 + w1) + (w2 + w3);
        ax = fmaf(w0, h0.x, ax); ay = fmaf(w0, h0.y, ay);
        az = fmaf(w0, h0.z, az); aw = fmaf(w0, h0.w, aw);
        ax = fmaf(w1, h1.x, ax); ay = fmaf(w1, h1.y, ay);
        az = fmaf(w1, h1.z, az); aw = fmaf(w1, h1.w, aw);
        ax = fmaf(w2, h2.x, ax); ay = fmaf(w2, h2.y, ay);
        az = fmaf(w2, h2.z, az); aw = fmaf(w2, h2.w, aw);
        ax = fmaf(w3, h3.x, ax); ay = fmaf(w3, h3.y, ay);
        az = fmaf(w3, h3.z, az); aw = fmaf(w3, h3.w, aw);
    }
    for (; p < pend; ++p) {
        int s = __ldg(g_srcs + p);
        float w = __expf(lrelu(__ldg(g_as1 + s * 4 + head) + adh));
        den += w;
        float4 h = *(const float4*)(g_h1 + (size_t)s * 128 + c0);
        ax = fmaf(w, h.x, ax); ay = fmaf(w, h.y, ay);
        az = fmaf(w, h.z, az); aw = fmaf(w, h.w, aw);
    }
    float inv = 1.f / (den + 1e-16f);
    float4 bb = *(const float4*)(b1 + c0);
    float v0 = fmaxf(ax * inv + bb.x, 0.f);
    float v1 = fmaxf(ay * inv + bb.y, 0.f);
    float v2 = fmaxf(az * inv + bb.z, 0.f);
    float v3 = fmaxf(aw * inv + bb.w, 0.f);
    float4 wA = *(const float4*)(W2 + c0 * 2);
    float4 wB = *(const float4*)(W2 + c0 * 2 + 4);
    float pq0 = v0 * wA.x + v1 * wA.z + v2 * wB.x + v3 * wB.z;
    float pq1 = v0 * wA.y + v1 * wA.w + v2 * wB.y + v3 * wB.w;
    #pragma unroll
    for (int o = 16; o; o >>= 1) {
        pq0 += __shfl_down_sync(0xffffffffu, pq0, o);
        pq1 += __shfl_down_sync(0xffffffffu, pq1, o);
    }
    if (lane == 0) {
        g_h2[d * 2] = pq0; g_h2[d * 2 + 1] = pq1;
        g_as2[d] = pq0 * a_src2[0] + pq1 * a_src2[1];
        g_ad2[d] = pq0 * a_dst2[0] + pq1 * a_dst2[1];
    }
}

// ---------------- kernel 5: layer2 gather -> output -------------------------
__global__ void k_gather2(float* __restrict__ out, const float* __restrict__ b2,
                          int n_nodes) {
    int t = blockIdx.x * blockDim.x + threadIdx.x;
    int d = t >> 5, lane = t & 31;
    if (d >= n_nodes) return;
    float add = g_ad2[d];
    float wsum = 0.f, s0 = 0.f, s1 = 0.f;
    int p0 = g_row[d], pend = g_row[d + 1];
    for (int p = p0 + lane; p < pend; p += 32) {
        int s = __ldg(g_srcs + p);
        float w = __expf(lrelu(__ldg(g_as2 + s) + add));
        wsum += w;
        float2 h = *(const float2*)(g_h2 + s * 2);
        s0 = fmaf(w, h.x, s0);
        s1 = fmaf(w, h.y, s1);
    }
    #pragma unroll
    for (int o = 16; o; o >>= 1) {
        wsum += __shfl_down_sync(0xffffffffu, wsum, o);
        s0   += __shfl_down_sync(0xffffffffu, s0, o);
        s1   += __shfl_down_sync(0xffffffffu, s1, o);
    }
    if (lane == 0) {
        float inv = 1.f / (wsum + 1e-16f);
        out[d * 2]     = s0 * inv + b2[0];
        out[d * 2 + 1] = s1 * inv + b2[1];
    }
}

extern "C" void kernel_launch(void* const* d_in, const int* in_sizes, int n_in,
                              void* d_out, int out_size) {
    const float* x   = (const float*)d_in[0];
    const int*   ei  = (const int*)d_in[1];
    const float* W1  = (const float*)d_in[2];
    const float* as1 = (const float*)d_in[3];
    const float* ad1 = (const float*)d_in[4];
    const float* b1  = (const float*)d_in[5];
    const float* W2  = (const float*)d_in[6];
    const float* as2 = (const float*)d_in[7];
    const float* ad2 = (const float*)d_in[8];
    const float* b2  = (const float*)d_in[9];
    float* out = (float*)d_out;

    int n  = in_sizes[0] / 16;   // nodes
    int Eo = in_sizes[1] / 2;    // original edges
    int ET = Eo + n;

    k_feathist<<<FB + HB, 256>>>(x, ei, W1, as1, ad1, n, Eo);
    k_scan<<<NCHUNK, 256>>>(n);
    k_scatter<<<(ET / 4 + 255) / 256 + 1, 256>>>(ei, Eo, n);
    int warps_grid = (n * 32 + 255) / 256;
    k_gather1<<<warps_grid, 256>>>(b1, W2, as2, ad2, n);
    k_gather2<<<warps_grid, 256>>>(out, b2, n);
}